// round 17
// baseline (speedup 1.0000x reference)
#include <cuda_runtime.h>
#include <cstdint>

#define Bn 64
#define Tn 64
#define Dn 64
#define Pn 63
typedef unsigned long long ull;

// ---------------- device scratch ----------------
__device__ __align__(16) float g_emb[Tn * Bn * 128];         // [t][b][e]
__device__ __align__(16) ull   g_embP[Tn * 32 * 128];        // [t][rpg][e]
__device__ __align__(16) ull   g_giP[64 * 2 * 32 * 3 * 128]; // [t][gru][rpg][gate][k]
__device__ __align__(16) ull   g_xP[64 * 32 * 64];           // [j][bp][d]
__device__ __align__(16) float g_WiaT[128 * 384];            // [e][u]
__device__ __align__(16) float g_WibT[128 * 384];
// combined slices: [sidx 8][tile 16][ Wh: li8 x 96 | Wb: li8 x 32 ] = 1024 floats (4KB)
__device__ __align__(16) float g_WC[8 * 16 * 1024];
__device__ __align__(16) float g_WembT[64 * 128];            // [d][e]
__device__ __align__(16) float g_WoWemb[128 * 64];           // [e][d]

// ---------------- f32x2 helpers ----------------
__device__ __forceinline__ ull pack2(float x, float y) {
    ull r; asm("mov.b64 %0, {%1,%2};" : "=l"(r) : "f"(x), "f"(y)); return r;
}
__device__ __forceinline__ float2 unpack2(ull v) {
    float2 r; asm("mov.b64 {%0,%1}, %2;" : "=f"(r.x), "=f"(r.y) : "l"(v)); return r;
}
__device__ __forceinline__ ull fma2(ull a, ull b, ull c) {
    ull d; asm("fma.rn.f32x2 %0, %1, %2, %3;" : "=l"(d) : "l"(a), "l"(b), "l"(c)); return d;
}
__device__ __forceinline__ ull mul2(ull a, ull b) {
    ull d; asm("mul.rn.f32x2 %0, %1, %2;" : "=l"(d) : "l"(a), "l"(b)); return d;
}
__device__ __forceinline__ ull add2(ull a, ull b) {
    ull d; asm("add.rn.f32x2 %0, %1, %2;" : "=l"(d) : "l"(a), "l"(b)); return d;
}
__device__ __forceinline__ float sigmoidf_(float v) {
    return __fdividef(1.f, 1.f + __expf(-v));
}
__device__ __forceinline__ float tanhfast(float v) {
    float e = __expf(2.f * v);
    return 1.f - __fdividef(2.f, e + 1.f);
}
__device__ __forceinline__ float gru_step(float ir, float iz, float in_,
                                          float hr, float hz, float hn, float h) {
    float r = sigmoidf_(ir + hr);
    float z = sigmoidf_(iz + hz);
    float n = tanhfast(in_ + r * hn);
    return n + z * (h - n);
}

// ---------------- cp.async helpers ----------------
__device__ __forceinline__ void cp16(uint32_t dst, const void* src) {
    asm volatile("cp.async.cg.shared.global [%0], [%1], 16;\n" :: "r"(dst), "l"(src));
}
__device__ __forceinline__ void cp_commit() {
    asm volatile("cp.async.commit_group;\n" ::: "memory");
}
__device__ __forceinline__ void cp_wait1() {
    asm volatile("cp.async.wait_group 1;\n" ::: "memory");
}
__device__ __forceinline__ void cp_wait0() {
    asm volatile("cp.async.wait_group 0;\n" ::: "memory");
}

// ---------------- prep ----------------
__global__ void prep_transpose(const float* __restrict__ x,
                               const float* __restrict__ Wh_a,
                               const float* __restrict__ Wh_b,
                               const float* __restrict__ Wi_a,
                               const float* __restrict__ Wi_b,
                               const float* __restrict__ Wb,
                               const float* __restrict__ W_emb,
                               const float* __restrict__ Wo) {
    int idx = blockIdx.x * blockDim.x + threadIdx.x;
    int stride = gridDim.x * blockDim.x;
    for (int n = idx; n < 128 * 384; n += stride) {
        int u = n % 384, i = n / 384;
        g_WiaT[n] = Wi_a[u * 128 + i];
        g_WibT[n] = Wi_b[u * 128 + i];
    }
    // Wh part: slice sidx = gru*4+band; tile tl = i>>3, li = i&7
    for (int n = idx; n < 8 * 128 * 32; n += stride) {
        int sidx = n >> 12;
        int rem = n & 4095;
        int i = rem >> 5, kk = rem & 31;
        int gru = sidx >> 2, band = sidx & 3;
        int kq = band * 32 + kk;
        const float* Wh = gru ? Wh_b : Wh_a;
        float wr = Wh[kq * 128 + i];
        float wz = Wh[(128 + kq) * 128 + i];
        float wn = Wh[(256 + kq) * 128 + i];
        int tl = i >> 3, li = i & 7;
        int bas = (sidx * 16 + tl) * 1024 + li * 96;
        g_WC[bas + 2 * kk]     = wr;
        g_WC[bas + 2 * kk + 1] = wz;
        g_WC[bas + 64 + kk]    = wn;
    }
    // Wb part (duplicated across gru halves)
    for (int n = idx; n < 8 * 128 * 32; n += stride) {
        int sidx = n >> 12;
        int rem = n & 4095;
        int i = rem >> 5, kk = rem & 31;
        int band = sidx & 3;
        int tl = i >> 3, li = i & 7;
        g_WC[(sidx * 16 + tl) * 1024 + 768 + li * 32 + kk] =
            Wb[(band * 32 + kk) * 128 + i];
    }
    for (int n = idx; n < 64 * 128; n += stride) {
        int e = n % 128, d = n / 128;
        g_WembT[n] = W_emb[e * 64 + d];
    }
    for (int n = idx; n < 128 * 64; n += stride) {
        int d = n % 64, e = n / 64;
        g_WoWemb[n] = Wo[e] * W_emb[e * 64 + d];
    }
    for (int n = idx; n < 64 * 32 * 64; n += stride) {
        int j = n >> 11;
        int bp = (n >> 6) & 31;
        int d = n & 63;
        float x0 = x[((size_t)(2 * bp) * Tn + j) * Dn + d];
        float x1 = x[((size_t)(2 * bp + 1) * Tn + j) * Dn + d];
        g_xP[n] = pack2(x0, x1);
    }
}

// ---------------- emb ----------------
__global__ void emb_kernel(const float* __restrict__ x, const float* __restrict__ b_emb) {
    __shared__ float xs[64];
    int tb = blockIdx.x;
    int t_ = tb >> 6, b = tb & 63;
    int e = threadIdx.x;
    if (e < 64) xs[e] = x[((size_t)b * Tn + t_) * Dn + e];
    __syncthreads();
    float acc = 0.f;
#pragma unroll 8
    for (int d = 0; d < 64; ++d) acc = fmaf(g_WembT[d * 128 + e], xs[d], acc);
    g_emb[(size_t)tb * 128 + e] = acc + b_emb[e];
}

// ---------------- gi (packed) + emb packing ----------------
__global__ void gi_kernel(const float* __restrict__ bi_a, const float* __restrict__ bi_b) {
    __shared__ float es[128];
    int tb = blockIdx.x;
    int t_ = tb >> 6, b = tb & 63;
    int t = threadIdx.x;
    if (t < 128) es[t] = g_emb[(size_t)tb * 128 + t];
    __syncthreads();
    float* gf = (float*)g_giP;
    for (int u = t; u < 768; u += 256) {
        const float* WT;
        const float* bi;
        int gru, uu;
        if (u < 384) { WT = g_WiaT; bi = bi_a; gru = 0; uu = u; }
        else         { WT = g_WibT; bi = bi_b; gru = 1; uu = u - 384; }
        float acc = 0.f;
#pragma unroll 8
        for (int e = 0; e < 128; ++e) acc = fmaf(WT[e * 384 + uu], es[e], acc);
        int gate = uu >> 7, k = uu & 127;
        size_t ullIdx = (((size_t)(t_ * 2 + gru) * 32 + (b >> 1)) * 3 + gate) * 128 + k;
        gf[ullIdx * 2 + (b & 1)] = acc + bi[uu];
    }
    if ((b & 1) == 0 && t < 128) {
        g_embP[((size_t)t_ * 32 + (b >> 1)) * 128 + t] =
            pack2(g_emb[(size_t)tb * 128 + t], g_emb[(size_t)(tb + 1) * 128 + t]);
    }
}

// ---------------- main persistent kernel ----------------
// 512 threads, 16 warps (4/SMSP). Warp = (rph, gru, band); each warp does its
// 4 row-pairs over the full i reduction. One barrier per step; epilogue
// pipelined one step; per-warp 2-slot x 4KB combined-tile rings.
#define RING_OFF   0                  // 16 warps x 2 slots x 4096 = 131072
#define SHH_OFF    131072             // ull [2][2][128][8] = 32768
#define BETA_OFF   163840             // ull [2][8][128] = 16384
#define WOW_OFF    180224             // float [128][64] = 32768
#define SCAL_OFF   212992             // preA[2][16], l[16], Wa[128]
#define SMEM_TOTAL 214016

__global__ __launch_bounds__(512, 1) void retain_main(
    const float* __restrict__ bh_a, const float* __restrict__ bh_b,
    const float* __restrict__ Wa, const float* __restrict__ ba,
    const float* __restrict__ bb, const float* __restrict__ Wo,
    const float* __restrict__ bo, int nq, float* __restrict__ out) {

    extern __shared__ char dsm[];
    float* smw = (float*)dsm;
    ull (*sh_h)[2][128][8]    = (ull (*)[2][128][8])(dsm + SHH_OFF);
    ull (*sh_betaP)[8][128]   = (ull (*)[8][128])(dsm + BETA_OFF);
    float* sWo                = (float*)(dsm + WOW_OFF);
    float* sh_preA  = (float*)(dsm + SCAL_OFF);    // [2][16]
    float* sh_l     = sh_preA + 32;                // [16]
    float* sh_Wa    = sh_preA + 48;                // [128]

    const int t = threadIdx.x;
    const int pb = blockIdx.x >> 2;
    const int chunkI = blockIdx.x & 3;
    const int b0 = chunkI * 16;

    const int w = t >> 5;
    const int lane = t & 31;
    const int rph = w >> 3;            // row-pair half
    const int gru = (w >> 2) & 1;
    const int sidx = w & 7;            // weight slice (gru*4+band)
    const int k = t & 127;
    const int kk = lane;
    const int mb = rph * 4;            // my rp base
    const int bq = mb + 2 * (gru ^ 1); // my beta rp pair base
    const int rp6 = t >> 6;            // 0..7: e_chain / gacc row-pair
    const int d_ = t & 63;

    const float* bh = gru ? bh_b : bh_a;
    const float bhr = bh[k], bhz = bh[128 + k], bhn = bh[256 + k];
    const float ba0 = ba[0], bbk = bb[k];
    const int base = Pn - nq;

    for (int n = t; n < 8192; n += 512) sWo[n] = g_WoWemb[n];
    if (t < 128) sh_Wa[t] = Wa[t];

    const bool seg2 = (pb < 31) && (pb >= base);
    const int totalSteps = (63 - pb) + (seg2 ? pb + 1 : 0);
    const int totalTiles = 16 * totalSteps;

    uint32_t ringB = (uint32_t)__cvta_generic_to_shared(dsm) + (uint32_t)(w * 8192);
    int issIdx = 0, issM = 0, issSlot = 0, consSlot = 0;

#define ISSUE_ONE() do {                                                        \
        if (issIdx < totalTiles) {                                              \
            const char* _src = (const char*)g_WC + ((size_t)(sidx * 16 + issM)) * 4096; \
            uint32_t _d = ringB + (uint32_t)(issSlot * 4096);                   \
            for (int _o = lane * 16; _o < 4096; _o += 512) cp16(_d + _o, _src + _o); \
            cp_commit();                                                        \
            ++issIdx; if (++issM == 16) issM = 0; issSlot ^= 1;                 \
        }                                                                       \
    } while (0)

#define WAITC() do {                                                            \
        if (issIdx < totalTiles) cp_wait1(); else cp_wait0();                   \
        __syncwarp();                                                           \
    } while (0)

    ISSUE_ONE();
    ISSUE_ONE();

    ull aR[4], aZ[4], aN[4];   // gh accumulators, pipelined across steps
    ull gbuf[12];              // gi for the current step (my 4 rps)

    for (int seg = 0; seg < 2; ++seg) {
        const int p = seg ? pb : 62 - pb;
        if (seg && !seg2) break;

        for (int n = t; n < 2 * 128 * 8; n += 512)
            ((ull*)sh_h[0])[n] = 0ull;
        for (int n = t; n < 2 * 8 * 128; n += 512)
            ((ull*)sh_betaP)[n] = 0ull;
        if (t < 16) sh_preA[16 + t] = -1e30f;   // buf1: exp -> 0
        ull cacc[2] = {0ull, 0ull};
        ull gacc = 0ull;
        ull lacc = 0ull;
#pragma unroll
        for (int r = 0; r < 4; ++r) { aR[r] = 0ull; aZ[r] = 0ull; aN[r] = 0ull; }
        // prefetch gi for step 0 (j = p), my 4 rps
        {
            const ull* gb = g_giP + (((size_t)(p * 2 + gru) * 32 + (b0 >> 1) + mb) * 3) * 128 + k;
#pragma unroll
            for (int r = 0; r < 4; ++r) {
                gbuf[r * 3]     = gb[(size_t)r * 384];
                gbuf[r * 3 + 1] = gb[(size_t)r * 384 + 128];
                gbuf[r * 3 + 2] = gb[(size_t)r * 384 + 256];
            }
        }
        __syncthreads();

        for (int s = 0; s <= p; ++s) {
            const int j = p - s;
            const int cb = s & 1;
            const int pv = (s ^ 1) & 1;
            const ull (*cur)[8]  = sh_h[cb][gru];
            ull (*nxtg)[8]       = sh_h[cb ^ 1][gru];
            const ull (*nxtA)[8] = sh_h[cb ^ 1][0];
            const ull (*nxtB)[8] = sh_h[cb ^ 1][1];

            // ---- GRU(s): h(s+1) for my 4 rps at hidden k ----
            {
#pragma unroll
                for (int r = 0; r < 4; ++r) {
                    float2 gr = unpack2(gbuf[r * 3]);
                    float2 gz = unpack2(gbuf[r * 3 + 1]);
                    float2 gn = unpack2(gbuf[r * 3 + 2]);
                    float2 hr = unpack2(aR[r]);
                    float2 hz = unpack2(aZ[r]);
                    float2 hn = unpack2(aN[r]);
                    float2 ho = unpack2(cur[k][mb + r]);
                    float hx = gru_step(gr.x, gz.x, gn.x,
                                        hr.x + bhr, hz.x + bhz, hn.x + bhn, ho.x);
                    float hy = gru_step(gr.y, gz.y, gn.y,
                                        hr.y + bhr, hz.y + bhz, hn.y + bhn, ho.y);
                    nxtg[k][mb + r] = pack2(hx, hy);
                }
            }
            __syncthreads();   // BAR1: the ONLY barrier per step

            // ---- prefetch gi(s+1) + emb/x for step s-1 ----
            {
                int jn = (j > 0) ? j - 1 : 0;
                const ull* gb = g_giP + (((size_t)(jn * 2 + gru) * 32 + (b0 >> 1) + mb) * 3) * 128 + k;
#pragma unroll
                for (int r = 0; r < 4; ++r) {
                    gbuf[r * 3]     = gb[(size_t)r * 384];
                    gbuf[r * 3 + 1] = gb[(size_t)r * 384 + 128];
                    gbuf[r * 3 + 2] = gb[(size_t)r * 384 + 256];
                }
            }
            ull ebr[2], xr;
            {
                const int jp = j + 1;    // timestep of step s-1 (s=0: weight 0)
                const ull* ebp = g_embP + ((size_t)jp * 32 + (b0 >> 1) + bq) * 128 + k;
                ebr[0] = ebp[0];
                ebr[1] = ebp[128];
                xr = g_xP[((size_t)jp * 32 + (b0 >> 1) + rp6) * 64 + d_];
            }

            // ---- preA(s): warp w computes row w ----
            {
                float part = 0.f;
#pragma unroll
                for (int ii = 0; ii < 4; ++ii) {
                    int i = lane + 32 * ii;
                    float2 hv = unpack2(nxtA[i][w >> 1]);
                    part = fmaf(sh_Wa[i], (w & 1) ? hv.y : hv.x, part);
                }
#pragma unroll
                for (int o = 16; o; o >>= 1)
                    part += __shfl_xor_sync(0xffffffffu, part, o);
                if (lane == 0) sh_preA[cb * 16 + w] = fmaf(0.5f, part, ba0);
            }

            // ---- FUSED: gh(s+1) (12) + beta(s) (2) + e_chain(s-1) (8/tile) ----
#pragma unroll
            for (int r = 0; r < 4; ++r) { aR[r] = 0ull; aZ[r] = 0ull; aN[r] = 0ull; }
            ull bacc0 = 0ull, bacc1 = 0ull;
            ull ea = 0ull;
            const ull* bpp = sh_betaP[pv][rp6];
            const float* wcp = sWo + d_;
#pragma unroll 1
            for (int tl = 0; tl < 16; ++tl) {
                WAITC();
                const float* wp = smw + w * 2048 + consSlot * 1024;
                consSlot ^= 1;
                const ull (*hrow)[8]  = (const ull (*)[8])&nxtg[tl * 8];
                const ull (*hrowB)[8] = &nxtB[tl * 8];
#pragma unroll
                for (int li = 0; li < 8; ++li) {
                    float2 rz = *(const float2*)(wp + li * 96 + 2 * kk);
                    float wnv = wp[li * 96 + 64 + kk];
                    float wbv = wp[768 + li * 32 + kk];
                    ull wr2 = pack2(rz.x, rz.x), wz2 = pack2(rz.y, rz.y);
                    ull wn2 = pack2(wnv, wnv), wb2 = pack2(wbv, wbv);
                    const ulonglong2* hp =
                        reinterpret_cast<const ulonglong2*>(hrow[li] + mb);
                    ulonglong2 hA = hp[0], hB = hp[1];
                    ulonglong2 hq =
                        *reinterpret_cast<const ulonglong2*>(hrowB[li] + bq);
                    aR[0] = fma2(wr2, hA.x, aR[0]); aZ[0] = fma2(wz2, hA.x, aZ[0]); aN[0] = fma2(wn2, hA.x, aN[0]);
                    bacc0 = fma2(wb2, hq.x, bacc0);
                    aR[1] = fma2(wr2, hA.y, aR[1]); aZ[1] = fma2(wz2, hA.y, aZ[1]); aN[1] = fma2(wn2, hA.y, aN[1]);
                    bacc1 = fma2(wb2, hq.y, bacc1);
                    aR[2] = fma2(wr2, hB.x, aR[2]); aZ[2] = fma2(wz2, hB.x, aZ[2]); aN[2] = fma2(wn2, hB.x, aN[2]);
                    aR[3] = fma2(wr2, hB.y, aR[3]); aZ[3] = fma2(wz2, hB.y, aZ[3]); aN[3] = fma2(wn2, hB.y, aN[3]);
                }
                // interleaved e_chain(s-1), 8 e per tile
#pragma unroll
                for (int ee = 0; ee < 8; ++ee) {
                    int e = tl * 8 + ee;
                    float wc = wcp[e * 64];
                    ea = fma2(pack2(wc, wc), bpp[e], ea);
                }
                ISSUE_ONE();
            }

            // ---- accum(s-1), unnormalized ----
            {
                const float* pap = sh_preA + pv * 16;
                ull wg = pack2(__expf(pap[2 * rp6]), __expf(pap[2 * rp6 + 1]));
                lacc = add2(lacc, wg);
#pragma unroll
                for (int c = 0; c < 2; ++c) {
                    int rp = bq + c;
                    ull wcv = pack2(__expf(pap[2 * rp]), __expf(pap[2 * rp + 1]));
                    ull btv = sh_betaP[pv][rp][k];
                    cacc[c] = fma2(mul2(wcv, btv), ebr[c], cacc[c]);
                }
                gacc = fma2(mul2(wg, ea), xr, gacc);
            }

            // ---- beta(s) tanh -> sh_betaP[cb] (my rp pair) ----
            {
                float2 v0 = unpack2(bacc0), v1 = unpack2(bacc1);
                sh_betaP[cb][bq][k] =
                    pack2(tanhfast(fmaf(0.5f, v0.x, bbk)), tanhfast(fmaf(0.5f, v0.y, bbk)));
                sh_betaP[cb][bq + 1][k] =
                    pack2(tanhfast(fmaf(0.5f, v1.x, bbk)), tanhfast(fmaf(0.5f, v1.y, bbk)));
            }
        } // steps

        // ---- epilogue: drain attention step p (j = 0) ----
        __syncthreads();
        {
            const int pvp = p & 1;
            ull ebr[2], xr;
            const ull* ebp = g_embP + ((size_t)(b0 >> 1) + bq) * 128 + k;
            ebr[0] = ebp[0];
            ebr[1] = ebp[128];
            xr = g_xP[((size_t)(b0 >> 1) + rp6) * 64 + d_];

            ull ea = 0ull;
            const ull* bpp = sh_betaP[pvp][rp6];
            const float* wcp = sWo + d_;
#pragma unroll 4
            for (int e = 0; e < 128; ++e) {
                float wc = wcp[e * 64];
                ea = fma2(pack2(wc, wc), bpp[e], ea);
            }
            const float* pap = sh_preA + pvp * 16;
            ull wg = pack2(__expf(pap[2 * rp6]), __expf(pap[2 * rp6 + 1]));
            lacc = add2(lacc, wg);
#pragma unroll
            for (int c = 0; c < 2; ++c) {
                int rp = bq + c;
                ull wcv = pack2(__expf(pap[2 * rp]), __expf(pap[2 * rp + 1]));
                ull btv = sh_betaP[pvp][rp][k];
                cacc[c] = fma2(mul2(wcv, btv), ebr[c], cacc[c]);
            }
            gacc = fma2(mul2(wg, ea), xr, gacc);
        }
        __syncthreads();

        // ---- finalize ----
        if (p >= base) {
            const int qi = p - base;
            sh_betaP[0][bq][k] = cacc[0];
            sh_betaP[0][bq + 1][k] = cacc[1];
            if (d_ == 0) {                 // one writer per rp6
                float2 lv = unpack2(lacc);
                sh_l[2 * rp6] = lv.x;
                sh_l[2 * rp6 + 1] = lv.y;
            }
            __syncthreads();

            if (t < 16) {
                float sum = 0.f;
                const ull* Crow = sh_betaP[0][t >> 1];
                const bool hi = (t & 1);
#pragma unroll 8
                for (int e = 0; e < 128; ++e) {
                    float2 v = unpack2(Crow[e]);
                    sum = fmaf(Wo[e], hi ? v.y : v.x, sum);
                }
                out[(size_t)(b0 + t) * nq + qi] = __fdividef(sum, sh_l[t]) + bo[0];
            }
            {
                float inv = __fdividef(1.f, (float)(p + 1));
                size_t wbase = (size_t)64 * nq;
                float2 gv = unpack2(gacc);
                float2 lv = unpack2(lacc);
                out[wbase + ((size_t)(b0 + 2 * rp6) * nq + qi) * 64 + d_] =
                    __fdividef(gv.x, lv.x) * inv;
                out[wbase + ((size_t)(b0 + 2 * rp6 + 1) * nq + qi) * 64 + d_] =
                    __fdividef(gv.y, lv.y) * inv;
            }
        }
        __syncthreads();
    } // segments
#undef WAITC
#undef ISSUE_ONE
}

// ---------------- launch ----------------
extern "C" void kernel_launch(void* const* d_in, const int* in_sizes, int n_in,
                              void* d_out, int out_size) {
    const float* x     = (const float*)d_in[0];
    const float* W_emb = (const float*)d_in[1];
    const float* b_emb = (const float*)d_in[2];
    const float* Wi_a  = (const float*)d_in[3];
    const float* Wh_a  = (const float*)d_in[4];
    const float* bi_a  = (const float*)d_in[5];
    const float* bh_a  = (const float*)d_in[6];
    const float* Wi_b  = (const float*)d_in[7];
    const float* Wh_b  = (const float*)d_in[8];
    const float* bi_b  = (const float*)d_in[9];
    const float* bh_b  = (const float*)d_in[10];
    const float* Wa    = (const float*)d_in[11];
    const float* ba    = (const float*)d_in[12];
    const float* Wb    = (const float*)d_in[13];
    const float* bb    = (const float*)d_in[14];
    const float* Wo    = (const float*)d_in[15];
    const float* bo    = (const float*)d_in[16];
    float* out = (float*)d_out;

    int nq = out_size / (64 * 65);

    static int smem_set = 0;
    if (!smem_set) {
        cudaFuncSetAttribute(retain_main,
                             cudaFuncAttributeMaxDynamicSharedMemorySize, SMEM_TOTAL);
        smem_set = 1;
    }

    prep_transpose<<<256, 256>>>(x, Wh_a, Wh_b, Wi_a, Wi_b, Wb, W_emb, Wo);
    emb_kernel<<<Tn * Bn, 128>>>(x, b_emb);
    gi_kernel<<<Tn * Bn, 256>>>(bi_a, bi_b);
    retain_main<<<128, 512, SMEM_TOTAL>>>(bh_a, bh_b, Wa, ba, bb, Wo, bo, nq, out);
}